// round 4
// baseline (speedup 1.0000x reference)
#include <cuda_runtime.h>
#include <cstdint>

// DynamicTopGate: h = tanh(x @ W1^T); logits = (h @ W2^T)/0.7; full argsort of
// 16 logits; softmax; cumulative-prob dynamic-k; outputs (idx, scores, mask, k)
// concatenated as float32 into d_out: [B*8 | B*8 | B*8 | B].
//
// GEMM1 is the whole cost: x[16384,2048] streamed once (134 MB). Round-3 ncu
// showed DRAM-latency bound (1 TB/s achieved, nothing saturated). This version
// stages x through SMEM with per-warp private 4-stage cp.async ring buffers to
// get ~100+ KB/SM in flight, while keeping the f32x2-packed FFMA accumulators.

#define IN_DIM  2048
#define NE      16
#define CHUNK   256                 // columns per pipeline stage
#define NSTAGES 4
#define NCHUNK  (IN_DIM / CHUNK)    // 8

typedef unsigned long long u64;

// Packed f32x2 FMA (Blackwell): 2 FMAs per instruction.
__device__ __forceinline__ u64 ffma2(u64 a, u64 b, u64 c) {
    u64 d;
    asm("fma.rn.f32x2 %0, %1, %2, %3;" : "=l"(d) : "l"(a), "l"(b), "l"(c));
    return d;
}

__device__ __forceinline__ void unpack2(u64 a, float& lo, float& hi) {
    asm("mov.b64 {%0, %1}, %2;" : "=f"(lo), "=f"(hi) : "l"(a));
}

__device__ __forceinline__ void cp16(uint32_t smem_dst, const void* gmem_src) {
    asm volatile("cp.async.cg.shared.global [%0], [%1], 16;\n"
                 :: "r"(smem_dst), "l"(gmem_src));
}
__device__ __forceinline__ void cp_commit() {
    asm volatile("cp.async.commit_group;\n" ::: "memory");
}
template <int N>
__device__ __forceinline__ void cp_wait() {
    asm volatile("cp.async.wait_group %0;\n" :: "n"(N) : "memory");
}

// Descending compare-exchange, stable (index-ascending) tie-break,
// matching jnp.argsort(-logits).
#define CE(a, b) do {                                                \
    float va = v[a], vb = v[b]; int ia = id[a], ib = id[b];          \
    bool sw = (vb > va) || (vb == va && ib < ia);                    \
    v[a] = sw ? vb : va; v[b] = sw ? va : vb;                        \
    id[a] = sw ? ib : ia; id[b] = sw ? ia : ib;                      \
} while (0);

__global__ void __launch_bounds__(128, 3)
gate_kernel(const float* __restrict__ x, const float* __restrict__ W1,
            const float* __restrict__ W2, float* __restrict__ out, int B)
{
    extern __shared__ float smem[];   // [4 warps][NSTAGES][4 rows][CHUNK]

    const int lane = threadIdx.x & 31;
    const int wIn  = threadIdx.x >> 5;
    const int gw   = blockIdx.x * 4 + wIn;
    const int row0 = gw * 4;
    if (row0 >= B) return;

    float* wbuf = smem + wIn * (NSTAGES * 4 * CHUNK);
    const uint32_t wbase = (uint32_t)__cvta_generic_to_shared(wbuf);

    // cp.async lane mapping: lane l copies row (l>>3), float4 slots (l&7)+8j.
    const int crow = lane >> 3;
    const int cseg = lane & 7;
    const float* gsrc = x + (size_t)(row0 + crow) * IN_DIM + cseg * 4;

    const float4* wp = reinterpret_cast<const float4*>(W1) + lane;

    // acc[r][e]: packed (even-col, odd-col) partial sums.
    u64 acc[4][NE];
    #pragma unroll
    for (int r = 0; r < 4; ++r)
        #pragma unroll
        for (int e = 0; e < NE; ++e) acc[r][e] = 0ull;

    // ---- pipeline prologue: issue chunks 0..NSTAGES-2 ----
    #pragma unroll
    for (int s = 0; s < NSTAGES - 1; ++s) {
        const float* src = gsrc + s * CHUNK;
        #pragma unroll
        for (int j = 0; j < 8; ++j)
            cp16(wbase + s * 4096 + crow * 1024 + (cseg + 8 * j) * 16,
                 src + j * 32);
        cp_commit();
    }

    // ---- main loop over 8 chunks of 256 columns ----
    #pragma unroll 1
    for (int c = 0; c < NCHUNK; ++c) {
        const int cp = c + NSTAGES - 1;
        if (cp < NCHUNK) {
            const int s = cp & (NSTAGES - 1);
            const float* src = gsrc + cp * CHUNK;
            #pragma unroll
            for (int j = 0; j < 8; ++j)
                cp16(wbase + s * 4096 + crow * 1024 + (cseg + 8 * j) * 16,
                     src + j * 32);
        }
        cp_commit();                 // commit every iter (possibly empty group)
        cp_wait<NSTAGES - 1>();      // chunk c complete (in-order groups)
        __syncwarp();

        const float* sb = wbuf + (c & (NSTAGES - 1)) * (4 * CHUNK);

        #pragma unroll
        for (int g = 0; g < 2; ++g) {            // two 128-col halves
            const int cg = c * 2 + g;            // global 128-col group index
            u64 xl[4], xh[4];
            #pragma unroll
            for (int r = 0; r < 4; ++r) {
                float4 xv = *reinterpret_cast<const float4*>(
                    sb + r * CHUNK + g * 128 + lane * 4);
                const u64* pv = reinterpret_cast<const u64*>(&xv);
                xl[r] = pv[0]; xh[r] = pv[1];
            }
            #pragma unroll
            for (int e = 0; e < NE; ++e) {
                float4 wv = __ldg(wp + e * (IN_DIM / 4) + cg * 32);  // L1-resident
                const u64* pw = reinterpret_cast<const u64*>(&wv);
                u64 wl = pw[0], wh = pw[1];
                #pragma unroll
                for (int r = 0; r < 4; ++r) acc[r][e] = ffma2(xl[r], wl, acc[r][e]);
                #pragma unroll
                for (int r = 0; r < 4; ++r) acc[r][e] = ffma2(xh[r], wh, acc[r][e]);
            }
        }
        __syncwarp();                // all lanes done reading before stage reuse
    }

    // ---- warp-reduce each (row, expert) partial; lane r keeps row r ----
    float myh[NE];
    #pragma unroll
    for (int e = 0; e < NE; ++e) {
        float s[4];
        #pragma unroll
        for (int r = 0; r < 4; ++r) {
            float lo, hi; unpack2(acc[r][e], lo, hi);
            float t = lo + hi;
            #pragma unroll
            for (int off = 16; off > 0; off >>= 1)
                t += __shfl_xor_sync(0xffffffffu, t, off);
            s[r] = t;
        }
        myh[e] = (lane == 0) ? s[0] : (lane == 1) ? s[1] : (lane == 2) ? s[2] : s[3];
    }

    if (lane < 4) {
        const int row = row0 + lane;

        float h[NE];
        #pragma unroll
        for (int e = 0; e < NE; ++e) h[e] = tanhf(myh[e]);

        // logits[f] = (sum_e h[e] * W2[f, e]) / 0.7
        float v[NE]; int id[NE];
        const float4* W2v = reinterpret_cast<const float4*>(W2);
        #pragma unroll
        for (int f = 0; f < NE; ++f) {
            float s = 0.0f;
            #pragma unroll
            for (int q = 0; q < NE / 4; ++q) {
                float4 w = __ldg(W2v + f * (NE / 4) + q);
                s = fmaf(h[4 * q + 0], w.x, s);
                s = fmaf(h[4 * q + 1], w.y, s);
                s = fmaf(h[4 * q + 2], w.z, s);
                s = fmaf(h[4 * q + 3], w.w, s);
            }
            v[f] = s / 0.7f;
            id[f] = f;
        }

        // Batcher odd-even mergesort, n=16, 63 comparators, descending.
        CE(0,1) CE(2,3) CE(4,5) CE(6,7) CE(8,9) CE(10,11) CE(12,13) CE(14,15)
        CE(0,2) CE(1,3) CE(4,6) CE(5,7) CE(8,10) CE(9,11) CE(12,14) CE(13,15)
        CE(1,2) CE(5,6) CE(9,10) CE(13,14)
        CE(0,4) CE(1,5) CE(2,6) CE(3,7) CE(8,12) CE(9,13) CE(10,14) CE(11,15)
        CE(2,4) CE(3,5) CE(10,12) CE(11,13)
        CE(1,2) CE(3,4) CE(5,6) CE(9,10) CE(11,12) CE(13,14)
        CE(0,8) CE(1,9) CE(2,10) CE(3,11) CE(4,12) CE(5,13) CE(6,14) CE(7,15)
        CE(4,8) CE(5,9) CE(6,10) CE(7,11)
        CE(2,4) CE(3,5) CE(6,8) CE(7,9) CE(10,12) CE(11,13)
        CE(1,2) CE(3,4) CE(5,6) CE(7,8) CE(9,10) CE(11,12) CE(13,14)

        // Softmax over sorted logits (max = v[0]).
        float m = v[0];
        float p[NE]; float ssum = 0.0f;
        #pragma unroll
        for (int e = 0; e < NE; ++e) { p[e] = expf(v[e] - m); ssum += p[e]; }
        float inv = 1.0f / ssum;
        #pragma unroll
        for (int e = 0; e < NE; ++e) p[e] *= inv;

        // k from cumulative probability.
        int k = NE;
        float cum = 0.0f;
        #pragma unroll
        for (int e = 0; e < NE; ++e) {
            cum += p[e];
            if (k == NE && cum >= 0.92f) k = e + 1;
        }
        float p1 = p[0], p2 = p[1], p3 = p[2];
        if (p1 >= 0.46f && (p1 - p2) >= 0.1f) k = 1;
        if (k > 2 && ((p1 + p2) >= 0.82f || p3 <= 0.12f || (p2 - p3) <= 0.03f)) k = 2;
        if (k < 1) k = 1;
        if (k > 3) k = 3;

        float* oidx  = out;
        float* osc   = out + (size_t)B * 8;
        float* omask = out + (size_t)B * 16;
        float* okv   = out + (size_t)B * 24;
        #pragma unroll
        for (int j = 0; j < 8; ++j) {
            float msk = (j < k) ? 1.0f : 0.0f;
            oidx[row * 8 + j]  = (float)id[j];
            osc[row * 8 + j]   = p[j] * msk;
            omask[row * 8 + j] = msk;
        }
        okv[row] = (float)k;
    }
}

extern "C" void kernel_launch(void* const* d_in, const int* in_sizes, int n_in,
                              void* d_out, int out_size)
{
    const float* x  = (const float*)d_in[0];
    const float* W1 = (const float*)d_in[1];
    const float* W2 = (const float*)d_in[2];
    float* out = (float*)d_out;

    int B = in_sizes[0] / IN_DIM;                 // 16384
    int groups = (B + 3) / 4;                     // warps needed (4 rows/warp)
    int blocks = (groups + 3) / 4;                // 4 warps/block -> 1024

    const int smem_bytes = 4 * NSTAGES * 4 * CHUNK * (int)sizeof(float);  // 64 KB
    cudaFuncSetAttribute(gate_kernel,
                         cudaFuncAttributeMaxDynamicSharedMemorySize, smem_bytes);
    gate_kernel<<<blocks, 128, smem_bytes>>>(x, W1, W2, out, B);
}

// round 6
// speedup vs baseline: 1.0203x; 1.0203x over previous
#include <cuda_runtime.h>
#include <cstdint>

// DynamicTopGate: h = tanh(x @ W1^T); logits = (h @ W2^T)/0.7; full argsort of
// 16 logits; softmax; cumulative-prob dynamic-k; outputs (idx, scores, mask, k)
// concatenated as float32 into d_out: [B*8 | B*8 | B*8 | B].
//
// Round-4 lesson: 64KB smem/block * 3 blocks ate the L1 carveout and evicted
// the 128KB W1 working set (L2% up, fma% down). This version keeps the
// per-warp cp.async ring for x but shrinks it to 24KB/block (72KB/SM), leaving
// 156KB L1 for W1. x (cp.async.cg) bypasses L1 entirely.

#define IN_DIM  2048
#define NE      16
#define CHUNK   128                 // columns per pipeline stage
#define NSTAGES 3
#define NCHUNK  (IN_DIM / CHUNK)    // 16

typedef unsigned long long u64;

// Packed f32x2 FMA (Blackwell): 2 FMAs per instruction.
__device__ __forceinline__ u64 ffma2(u64 a, u64 b, u64 c) {
    u64 d;
    asm("fma.rn.f32x2 %0, %1, %2, %3;" : "=l"(d) : "l"(a), "l"(b), "l"(c));
    return d;
}

__device__ __forceinline__ void unpack2(u64 a, float& lo, float& hi) {
    asm("mov.b64 {%0, %1}, %2;" : "=f"(lo), "=f"(hi) : "l"(a));
}

__device__ __forceinline__ void cp16(uint32_t smem_dst, const void* gmem_src) {
    asm volatile("cp.async.cg.shared.global [%0], [%1], 16;\n"
                 :: "r"(smem_dst), "l"(gmem_src));
}
__device__ __forceinline__ void cp_commit() {
    asm volatile("cp.async.commit_group;\n" ::: "memory");
}
template <int N>
__device__ __forceinline__ void cp_wait() {
    asm volatile("cp.async.wait_group %0;\n" :: "n"(N) : "memory");
}

// Descending compare-exchange, stable (index-ascending) tie-break,
// matching jnp.argsort(-logits).
#define CE(a, b) do {                                                \
    float va = v[a], vb = v[b]; int ia = id[a], ib = id[b];          \
    bool sw = (vb > va) || (vb == va && ib < ia);                    \
    v[a] = sw ? vb : va; v[b] = sw ? va : vb;                        \
    id[a] = sw ? ib : ia; id[b] = sw ? ia : ib;                      \
} while (0);

__global__ void __launch_bounds__(128, 3)
gate_kernel(const float* __restrict__ x, const float* __restrict__ W1,
            const float* __restrict__ W2, float* __restrict__ out, int B)
{
    extern __shared__ float smem[];   // [4 warps][NSTAGES][4 rows][CHUNK]

    const int lane = threadIdx.x & 31;
    const int wIn  = threadIdx.x >> 5;
    const int gw   = blockIdx.x * 4 + wIn;
    const int row0 = gw * 4;
    if (row0 >= B) return;

    float* wbuf = smem + wIn * (NSTAGES * 4 * CHUNK);
    const uint32_t wbase = (uint32_t)__cvta_generic_to_shared(wbuf);

    // cp.async lane mapping: lane l copies row (l>>3), float4 slots (l&7)+8j.
    const int crow = lane >> 3;
    const int cseg = lane & 7;
    const float* gsrc = x + (size_t)(row0 + crow) * IN_DIM + cseg * 4;

    const float4* wp = reinterpret_cast<const float4*>(W1) + lane;

    // acc[r][e]: packed (even-col, odd-col) partial sums.
    u64 acc[4][NE];
    #pragma unroll
    for (int r = 0; r < 4; ++r)
        #pragma unroll
        for (int e = 0; e < NE; ++e) acc[r][e] = 0ull;

    // Per-warp stage size: 4 rows * CHUNK floats = 2048 bytes.
    const int STAGE_B = 4 * CHUNK * 4;   // 2048
    const int ROW_B   = CHUNK * 4;       // 512

    // ---- pipeline prologue: issue chunks 0..NSTAGES-2 ----
    #pragma unroll
    for (int s = 0; s < NSTAGES - 1; ++s) {
        const float* src = gsrc + s * CHUNK;
        #pragma unroll
        for (int j = 0; j < 4; ++j)
            cp16(wbase + s * STAGE_B + crow * ROW_B + (cseg + 8 * j) * 16,
                 src + j * 32);
        cp_commit();
    }

    // ---- main loop over 16 chunks of 128 columns ----
    int s_fill = NSTAGES - 1;   // stage to fill next
    int s_read = 0;             // stage to consume
    #pragma unroll 1
    for (int c = 0; c < NCHUNK; ++c) {
        const int cpre = c + NSTAGES - 1;
        if (cpre < NCHUNK) {
            const float* src = gsrc + cpre * CHUNK;
            #pragma unroll
            for (int j = 0; j < 4; ++j)
                cp16(wbase + s_fill * STAGE_B + crow * ROW_B + (cseg + 8 * j) * 16,
                     src + j * 32);
        }
        cp_commit();                 // one group per iter (possibly empty)
        cp_wait<NSTAGES - 1>();      // chunk c complete (in-order groups)
        __syncwarp();

        const float* sb = wbuf + s_read * (4 * CHUNK);

        u64 xl[4], xh[4];
        #pragma unroll
        for (int r = 0; r < 4; ++r) {
            float4 xv = *reinterpret_cast<const float4*>(sb + r * CHUNK + lane * 4);
            const u64* pv = reinterpret_cast<const u64*>(&xv);
            xl[r] = pv[0]; xh[r] = pv[1];
        }
        #pragma unroll
        for (int e = 0; e < NE; ++e) {
            float4 wv = __ldg(wp + e * (IN_DIM / 4) + c * 32);   // L1-resident
            const u64* pw = reinterpret_cast<const u64*>(&wv);
            u64 wl = pw[0], wh = pw[1];
            #pragma unroll
            for (int r = 0; r < 4; ++r) acc[r][e] = ffma2(xl[r], wl, acc[r][e]);
            #pragma unroll
            for (int r = 0; r < 4; ++r) acc[r][e] = ffma2(xh[r], wh, acc[r][e]);
        }
        __syncwarp();                // all lanes done before stage reuse

        s_fill = (s_fill + 1 == NSTAGES) ? 0 : s_fill + 1;
        s_read = (s_read + 1 == NSTAGES) ? 0 : s_read + 1;
    }

    // ---- warp-reduce each (row, expert) partial; lane r keeps row r ----
    float myh[NE];
    #pragma unroll
    for (int e = 0; e < NE; ++e) {
        float s[4];
        #pragma unroll
        for (int r = 0; r < 4; ++r) {
            float lo, hi; unpack2(acc[r][e], lo, hi);
            float t = lo + hi;
            #pragma unroll
            for (int off = 16; off > 0; off >>= 1)
                t += __shfl_xor_sync(0xffffffffu, t, off);
            s[r] = t;
        }
        myh[e] = (lane == 0) ? s[0] : (lane == 1) ? s[1] : (lane == 2) ? s[2] : s[3];
    }

    if (lane < 4) {
        const int row = row0 + lane;

        float h[NE];
        #pragma unroll
        for (int e = 0; e < NE; ++e) h[e] = tanhf(myh[e]);

        // logits[f] = (sum_e h[e] * W2[f, e]) / 0.7
        float v[NE]; int id[NE];
        const float4* W2v = reinterpret_cast<const float4*>(W2);
        #pragma unroll
        for (int f = 0; f < NE; ++f) {
            float s = 0.0f;
            #pragma unroll
            for (int q = 0; q < NE / 4; ++q) {
                float4 w = __ldg(W2v + f * (NE / 4) + q);
                s = fmaf(h[4 * q + 0], w.x, s);
                s = fmaf(h[4 * q + 1], w.y, s);
                s = fmaf(h[4 * q + 2], w.z, s);
                s = fmaf(h[4 * q + 3], w.w, s);
            }
            v[f] = s / 0.7f;
            id[f] = f;
        }

        // Batcher odd-even mergesort, n=16, 63 comparators, descending.
        CE(0,1) CE(2,3) CE(4,5) CE(6,7) CE(8,9) CE(10,11) CE(12,13) CE(14,15)
        CE(0,2) CE(1,3) CE(4,6) CE(5,7) CE(8,10) CE(9,11) CE(12,14) CE(13,15)
        CE(1,2) CE(5,6) CE(9,10) CE(13,14)
        CE(0,4) CE(1,5) CE(2,6) CE(3,7) CE(8,12) CE(9,13) CE(10,14) CE(11,15)
        CE(2,4) CE(3,5) CE(10,12) CE(11,13)
        CE(1,2) CE(3,4) CE(5,6) CE(9,10) CE(11,12) CE(13,14)
        CE(0,8) CE(1,9) CE(2,10) CE(3,11) CE(4,12) CE(5,13) CE(6,14) CE(7,15)
        CE(4,8) CE(5,9) CE(6,10) CE(7,11)
        CE(2,4) CE(3,5) CE(6,8) CE(7,9) CE(10,12) CE(11,13)
        CE(1,2) CE(3,4) CE(5,6) CE(7,8) CE(9,10) CE(11,12) CE(13,14)

        // Softmax over sorted logits (max = v[0]).
        float m = v[0];
        float p[NE]; float ssum = 0.0f;
        #pragma unroll
        for (int e = 0; e < NE; ++e) { p[e] = expf(v[e] - m); ssum += p[e]; }
        float inv = 1.0f / ssum;
        #pragma unroll
        for (int e = 0; e < NE; ++e) p[e] *= inv;

        // k from cumulative probability.
        int k = NE;
        float cum = 0.0f;
        #pragma unroll
        for (int e = 0; e < NE; ++e) {
            cum += p[e];
            if (k == NE && cum >= 0.92f) k = e + 1;
        }
        float p1 = p[0], p2 = p[1], p3 = p[2];
        if (p1 >= 0.46f && (p1 - p2) >= 0.1f) k = 1;
        if (k > 2 && ((p1 + p2) >= 0.82f || p3 <= 0.12f || (p2 - p3) <= 0.03f)) k = 2;
        if (k < 1) k = 1;
        if (k > 3) k = 3;

        float* oidx  = out;
        float* osc   = out + (size_t)B * 8;
        float* omask = out + (size_t)B * 16;
        float* okv   = out + (size_t)B * 24;
        #pragma unroll
        for (int j = 0; j < 8; ++j) {
            float msk = (j < k) ? 1.0f : 0.0f;
            oidx[row * 8 + j]  = (float)id[j];
            osc[row * 8 + j]   = p[j] * msk;
            omask[row * 8 + j] = msk;
        }
        okv[row] = (float)k;
    }
}

extern "C" void kernel_launch(void* const* d_in, const int* in_sizes, int n_in,
                              void* d_out, int out_size)
{
    const float* x  = (const float*)d_in[0];
    const float* W1 = (const float*)d_in[1];
    const float* W2 = (const float*)d_in[2];
    float* out = (float*)d_out;

    int B = in_sizes[0] / IN_DIM;                 // 16384
    int groups = (B + 3) / 4;                     // warps needed (4 rows/warp)
    int blocks = (groups + 3) / 4;                // 4 warps/block -> 1024

    const int smem_bytes = 4 * NSTAGES * 4 * CHUNK * (int)sizeof(float);  // 24 KB
    cudaFuncSetAttribute(gate_kernel,
                         cudaFuncAttributeMaxDynamicSharedMemorySize, smem_bytes);
    gate_kernel<<<blocks, 128, smem_bytes>>>(x, W1, W2, out, B);
}

// round 7
// speedup vs baseline: 1.0532x; 1.0322x over previous
#include <cuda_runtime.h>
#include <cstdint>

// DynamicTopGate: h = tanh(x @ W1^T); logits = (h @ W2^T)/0.7; full argsort of
// 16 logits; softmax; cumulative-prob dynamic-k; outputs (idx, scores, mask, k)
// concatenated as float32 into d_out: [B*8 | B*8 | B*8 | B].
//
// Round-6 post-mortem: LDG/LDGSTS paths plateau at ~950 GB/s regardless of
// pipelining -> per-warp/LSU outstanding-request cap. This version streams x
// through the BULK-COPY (TMA) engine instead: per-warp double-buffered
// cp.async.bulk + mbarrier pipeline. W1 stays hot in L1 (static smem kept
// small: ~50 KB/SM -> 164 KB L1 carveout > 128 KB W1).

#define IN_DIM  2048
#define NE      16
#define CHUNK   128                 // columns per pipeline stage
#define NST     2                   // stages (double buffer)
#define NCHUNK  (IN_DIM / CHUNK)    // 16

typedef unsigned long long u64;

// Packed f32x2 FMA (Blackwell): 2 FMAs per instruction.
__device__ __forceinline__ u64 ffma2(u64 a, u64 b, u64 c) {
    u64 d;
    asm("fma.rn.f32x2 %0, %1, %2, %3;" : "=l"(d) : "l"(a), "l"(b), "l"(c));
    return d;
}
__device__ __forceinline__ void unpack2(u64 a, float& lo, float& hi) {
    asm("mov.b64 {%0, %1}, %2;" : "=f"(lo), "=f"(hi) : "l"(a));
}

__device__ __forceinline__ void mbar_init(uint32_t bar, uint32_t cnt) {
    asm volatile("mbarrier.init.shared.b64 [%0], %1;" :: "r"(bar), "r"(cnt) : "memory");
}
__device__ __forceinline__ void mbar_expect_tx(uint32_t bar, uint32_t bytes) {
    asm volatile("mbarrier.arrive.expect_tx.shared.b64 _, [%0], %1;"
                 :: "r"(bar), "r"(bytes) : "memory");
}
__device__ __forceinline__ void mbar_wait(uint32_t bar, uint32_t parity) {
    uint32_t done;
    asm volatile(
        "{\n\t.reg .pred p;\n\t"
        "mbarrier.try_wait.parity.acquire.cta.shared::cta.b64 p, [%1], %2;\n\t"
        "selp.b32 %0, 1, 0, p;\n\t}"
        : "=r"(done) : "r"(bar), "r"(parity) : "memory");
    if (!done) {
        asm volatile(
            "{\n\t.reg .pred P1;\n\t"
            "W_%=:\n\t"
            "mbarrier.try_wait.parity.acquire.cta.shared::cta.b64 P1, [%0], %1, 0x989680;\n\t"
            "@P1 bra.uni D_%=;\n\t"
            "bra.uni W_%=;\n\t"
            "D_%=:\n\t}"
            :: "r"(bar), "r"(parity) : "memory");
    }
}
__device__ __forceinline__ void bulk_cp(uint32_t dst, const void* src,
                                        uint32_t bytes, uint32_t bar) {
    asm volatile(
        "cp.async.bulk.shared::cta.global.mbarrier::complete_tx::bytes "
        "[%0], [%1], %2, [%3];"
        :: "r"(dst), "l"(src), "r"(bytes), "r"(bar) : "memory");
}

// Descending compare-exchange, stable (index-ascending) tie-break,
// matching jnp.argsort(-logits).
#define CE(a, b) do {                                                \
    float va = v[a], vb = v[b]; int ia = id[a], ib = id[b];          \
    bool sw = (vb > va) || (vb == va && ib < ia);                    \
    v[a] = sw ? vb : va; v[b] = sw ? va : vb;                        \
    id[a] = sw ? ib : ia; id[b] = sw ? ia : ib;                      \
} while (0);

__global__ void __launch_bounds__(128, 3)
gate_kernel(const float* __restrict__ x, const float* __restrict__ W1,
            const float* __restrict__ W2, float* __restrict__ out, int B)
{
    // Static smem: 4 warps * NST stages * 4 rows * CHUNK floats + barriers.
    __shared__ float       xbuf[4 * NST * 4 * CHUNK];     // 16 KB
    __shared__ __align__(8) u64 bars[4 * NST];            // 64 B

    const int lane = threadIdx.x & 31;
    const int wIn  = threadIdx.x >> 5;
    const int gw   = blockIdx.x * 4 + wIn;
    const int row0 = gw * 4;
    if (row0 >= B) return;

    float* wbuf = xbuf + wIn * (NST * 4 * CHUNK);
    const uint32_t dbase = (uint32_t)__cvta_generic_to_shared(wbuf);
    const uint32_t bbase = (uint32_t)__cvta_generic_to_shared(&bars[wIn * NST]);

    const float* gsrc = x + (size_t)row0 * IN_DIM;        // 4 contiguous rows
    const float4* wp  = reinterpret_cast<const float4*>(W1) + lane;

    const uint32_t STAGE_B = 4 * CHUNK * 4;   // 2048 bytes per stage
    const uint32_t ROW_B   = CHUNK * 4;       // 512 bytes per row-slice

    if (lane == 0) {
        mbar_init(bbase + 0, 1);
        mbar_init(bbase + 8, 1);
    }
    __syncwarp();
    asm volatile("fence.proxy.async.shared::cta;" ::: "memory");
    __syncwarp();

    // Prologue: fetch chunks 0 and 1 into stages 0 and 1.
    if (lane == 0) {
        #pragma unroll
        for (int s = 0; s < NST; ++s) {
            mbar_expect_tx(bbase + 8 * s, STAGE_B);
            #pragma unroll
            for (int r = 0; r < 4; ++r)
                bulk_cp(dbase + s * STAGE_B + r * ROW_B,
                        gsrc + (size_t)r * IN_DIM + s * CHUNK,
                        ROW_B, bbase + 8 * s);
        }
    }

    // acc[r][e]: packed (even-col, odd-col) partial sums.
    u64 acc[4][NE];
    #pragma unroll
    for (int r = 0; r < 4; ++r)
        #pragma unroll
        for (int e = 0; e < NE; ++e) acc[r][e] = 0ull;

    int ph[NST] = {0, 0};

    #pragma unroll 1
    for (int c = 0; c < NCHUNK; ++c) {
        const int s = c & (NST - 1);
        const uint32_t bar = bbase + 8 * s;

        mbar_wait(bar, ph[s]);
        ph[s] ^= 1;

        const float* sb = wbuf + s * (4 * CHUNK);
        u64 xl[4], xh[4];
        #pragma unroll
        for (int r = 0; r < 4; ++r) {
            float4 xv = *reinterpret_cast<const float4*>(sb + r * CHUNK + lane * 4);
            const u64* pv = reinterpret_cast<const u64*>(&xv);
            xl[r] = pv[0]; xh[r] = pv[1];
        }
        #pragma unroll
        for (int e = 0; e < NE; ++e) {
            float4 wv = __ldg(wp + e * (IN_DIM / 4) + c * 32);   // L1-resident
            const u64* pw = reinterpret_cast<const u64*>(&wv);
            u64 wl = pw[0], wh = pw[1];
            #pragma unroll
            for (int r = 0; r < 4; ++r) acc[r][e] = ffma2(xl[r], wl, acc[r][e]);
            #pragma unroll
            for (int r = 0; r < 4; ++r) acc[r][e] = ffma2(xh[r], wh, acc[r][e]);
        }
        __syncwarp();                // all lanes done reading before refill

        const int cn = c + NST;      // refill this stage with chunk c+NST
        if (cn < NCHUNK && lane == 0) {
            mbar_expect_tx(bar, STAGE_B);
            #pragma unroll
            for (int r = 0; r < 4; ++r)
                bulk_cp(dbase + s * STAGE_B + r * ROW_B,
                        gsrc + (size_t)r * IN_DIM + cn * CHUNK,
                        ROW_B, bar);
        }
    }

    // ---- warp-reduce each (row, expert) partial; lane r keeps row r ----
    float myh[NE];
    #pragma unroll
    for (int e = 0; e < NE; ++e) {
        float s[4];
        #pragma unroll
        for (int r = 0; r < 4; ++r) {
            float lo, hi; unpack2(acc[r][e], lo, hi);
            float t = lo + hi;
            #pragma unroll
            for (int off = 16; off > 0; off >>= 1)
                t += __shfl_xor_sync(0xffffffffu, t, off);
            s[r] = t;
        }
        myh[e] = (lane == 0) ? s[0] : (lane == 1) ? s[1] : (lane == 2) ? s[2] : s[3];
    }

    if (lane < 4) {
        const int row = row0 + lane;

        float h[NE];
        #pragma unroll
        for (int e = 0; e < NE; ++e) h[e] = tanhf(myh[e]);

        // logits[f] = (sum_e h[e] * W2[f, e]) / 0.7
        float v[NE]; int id[NE];
        const float4* W2v = reinterpret_cast<const float4*>(W2);
        #pragma unroll
        for (int f = 0; f < NE; ++f) {
            float s = 0.0f;
            #pragma unroll
            for (int q = 0; q < NE / 4; ++q) {
                float4 w = __ldg(W2v + f * (NE / 4) + q);
                s = fmaf(h[4 * q + 0], w.x, s);
                s = fmaf(h[4 * q + 1], w.y, s);
                s = fmaf(h[4 * q + 2], w.z, s);
                s = fmaf(h[4 * q + 3], w.w, s);
            }
            v[f] = s / 0.7f;
            id[f] = f;
        }

        // Batcher odd-even mergesort, n=16, 63 comparators, descending.
        CE(0,1) CE(2,3) CE(4,5) CE(6,7) CE(8,9) CE(10,11) CE(12,13) CE(14,15)
        CE(0,2) CE(1,3) CE(4,6) CE(5,7) CE(8,10) CE(9,11) CE(12,14) CE(13,15)
        CE(1,2) CE(5,6) CE(9,10) CE(13,14)
        CE(0,4) CE(1,5) CE(2,6) CE(3,7) CE(8,12) CE(9,13) CE(10,14) CE(11,15)
        CE(2,4) CE(3,5) CE(10,12) CE(11,13)
        CE(1,2) CE(3,4) CE(5,6) CE(9,10) CE(11,12) CE(13,14)
        CE(0,8) CE(1,9) CE(2,10) CE(3,11) CE(4,12) CE(5,13) CE(6,14) CE(7,15)
        CE(4,8) CE(5,9) CE(6,10) CE(7,11)
        CE(2,4) CE(3,5) CE(6,8) CE(7,9) CE(10,12) CE(11,13)
        CE(1,2) CE(3,4) CE(5,6) CE(7,8) CE(9,10) CE(11,12) CE(13,14)

        // Softmax over sorted logits (max = v[0]).
        float m = v[0];
        float p[NE]; float ssum = 0.0f;
        #pragma unroll
        for (int e = 0; e < NE; ++e) { p[e] = expf(v[e] - m); ssum += p[e]; }
        float inv = 1.0f / ssum;
        #pragma unroll
        for (int e = 0; e < NE; ++e) p[e] *= inv;

        // k from cumulative probability.
        int k = NE;
        float cum = 0.0f;
        #pragma unroll
        for (int e = 0; e < NE; ++e) {
            cum += p[e];
            if (k == NE && cum >= 0.92f) k = e + 1;
        }
        float p1 = p[0], p2 = p[1], p3 = p[2];
        if (p1 >= 0.46f && (p1 - p2) >= 0.1f) k = 1;
        if (k > 2 && ((p1 + p2) >= 0.82f || p3 <= 0.12f || (p2 - p3) <= 0.03f)) k = 2;
        if (k < 1) k = 1;
        if (k > 3) k = 3;

        float* oidx  = out;
        float* osc   = out + (size_t)B * 8;
        float* omask = out + (size_t)B * 16;
        float* okv   = out + (size_t)B * 24;
        #pragma unroll
        for (int j = 0; j < 8; ++j) {
            float msk = (j < k) ? 1.0f : 0.0f;
            oidx[row * 8 + j]  = (float)id[j];
            osc[row * 8 + j]   = p[j] * msk;
            omask[row * 8 + j] = msk;
        }
        okv[row] = (float)k;
    }
}

extern "C" void kernel_launch(void* const* d_in, const int* in_sizes, int n_in,
                              void* d_out, int out_size)
{
    const float* x  = (const float*)d_in[0];
    const float* W1 = (const float*)d_in[1];
    const float* W2 = (const float*)d_in[2];
    float* out = (float*)d_out;

    int B = in_sizes[0] / IN_DIM;                 // 16384
    int groups = (B + 3) / 4;                     // warps needed (4 rows/warp)
    int blocks = (groups + 3) / 4;                // 4 warps/block -> 1024

    gate_kernel<<<blocks, 128>>>(x, W1, W2, out, B);
}

// round 8
// speedup vs baseline: 1.9376x; 1.8398x over previous
#include <cuda_runtime.h>
#include <cstdint>

// DynamicTopGate, two-kernel version.
//
// Rounds 3-7 post-mortem: every load mechanism (LDG, cp.async, TMA bulk)
// plateaued at ~1 TB/s with DRAM 88% idle. Back-solved in-flight bytes show
// MLP_eff ~= 1: the 128-reg f32x2 asm accumulator block starved ptxas of
// registers to batch loads, and 12 warps/SM can't cover DRAM latency at MLP 1.
// This round: scalar accumulators (32 regs), plain-C fmaf (ptxas can pipeline),
// 20 warps/SM, and the serial per-row epilogue moved to its own
// one-thread-per-row kernel.

#define IN_DIM 2048
#define NE     16
#define BMAX   16384

__device__ float g_h[BMAX * NE];   // raw GEMM1 sums (pre-tanh), 1 MB scratch

// ---------------------------------------------------------------------------
// Kernel A: h_raw[b, e] = sum_i x[b, i] * W1[e, i]
// 2 rows per warp, scalar accumulators, warp-butterfly reduction.
// ---------------------------------------------------------------------------
__global__ void __launch_bounds__(128, 5)
gemm1_kernel(const float* __restrict__ x, const float* __restrict__ W1, int B)
{
    const int lane = threadIdx.x & 31;
    const int gw   = blockIdx.x * 4 + (threadIdx.x >> 5);
    const int row0 = gw * 2;
    if (row0 >= B) return;

    const float4* x0 = reinterpret_cast<const float4*>(x + (size_t)row0 * IN_DIM) + lane;
    const float4* x1 = x0 + (IN_DIM / 4);
    const float4* wp = reinterpret_cast<const float4*>(W1) + lane;

    float acc0[NE], acc1[NE];
    #pragma unroll
    for (int e = 0; e < NE; ++e) { acc0[e] = 0.0f; acc1[e] = 0.0f; }

    // 16 chunks of 128 columns; unroll 4 so ptxas front-batches x loads
    // (8 LDG.128 per unrolled body) while keeping the body I$-resident.
    #pragma unroll 4
    for (int c = 0; c < IN_DIM / 128; ++c) {
        float4 a0 = __ldcs(x0 + c * 32);     // streaming: don't pollute L1/L2
        float4 a1 = __ldcs(x1 + c * 32);
        #pragma unroll
        for (int e = 0; e < NE; ++e) {
            float4 w = __ldg(wp + e * (IN_DIM / 4) + c * 32);   // L1-resident
            acc0[e] = fmaf(a0.x, w.x, fmaf(a0.y, w.y,
                      fmaf(a0.z, w.z, fmaf(a0.w, w.w, acc0[e]))));
            acc1[e] = fmaf(a1.x, w.x, fmaf(a1.y, w.y,
                      fmaf(a1.z, w.z, fmaf(a1.w, w.w, acc1[e]))));
        }
    }

    // Butterfly-reduce each accumulator across the warp (all lanes get sums).
    #pragma unroll
    for (int e = 0; e < NE; ++e) {
        #pragma unroll
        for (int off = 16; off > 0; off >>= 1) {
            acc0[e] += __shfl_xor_sync(0xffffffffu, acc0[e], off);
            acc1[e] += __shfl_xor_sync(0xffffffffu, acc1[e], off);
        }
    }

    float4* hp = reinterpret_cast<float4*>(g_h + (size_t)row0 * NE);
    if (lane == 0) {
        hp[0] = make_float4(acc0[0],  acc0[1],  acc0[2],  acc0[3]);
        hp[1] = make_float4(acc0[4],  acc0[5],  acc0[6],  acc0[7]);
        hp[2] = make_float4(acc0[8],  acc0[9],  acc0[10], acc0[11]);
        hp[3] = make_float4(acc0[12], acc0[13], acc0[14], acc0[15]);
    } else if (lane == 1) {
        hp[4] = make_float4(acc1[0],  acc1[1],  acc1[2],  acc1[3]);
        hp[5] = make_float4(acc1[4],  acc1[5],  acc1[6],  acc1[7]);
        hp[6] = make_float4(acc1[8],  acc1[9],  acc1[10], acc1[11]);
        hp[7] = make_float4(acc1[12], acc1[13], acc1[14], acc1[15]);
    }
}

// ---------------------------------------------------------------------------
// Kernel B: per-row epilogue. tanh -> W2 -> /0.7 -> argsort16 -> softmax ->
// dynamic-k -> outputs. One thread per row.
// ---------------------------------------------------------------------------

// Descending compare-exchange, stable (index-ascending) tie-break,
// matching jnp.argsort(-logits).
#define CE(a, b) do {                                                \
    float va = v[a], vb = v[b]; int ia = id[a], ib = id[b];          \
    bool sw = (vb > va) || (vb == va && ib < ia);                    \
    v[a] = sw ? vb : va; v[b] = sw ? va : vb;                        \
    id[a] = sw ? ib : ia; id[b] = sw ? ia : ib;                      \
} while (0);

__global__ void __launch_bounds__(256)
epilogue_kernel(const float* __restrict__ W2, float* __restrict__ out, int B)
{
    const int row = blockIdx.x * blockDim.x + threadIdx.x;
    if (row >= B) return;

    float h[NE];
    const float4* hp = reinterpret_cast<const float4*>(g_h + (size_t)row * NE);
    #pragma unroll
    for (int q = 0; q < NE / 4; ++q) {
        float4 hv = hp[q];
        h[4 * q + 0] = tanhf(hv.x);
        h[4 * q + 1] = tanhf(hv.y);
        h[4 * q + 2] = tanhf(hv.z);
        h[4 * q + 3] = tanhf(hv.w);
    }

    // logits[f] = (sum_e h[e] * W2[f, e]) / 0.7
    float v[NE]; int id[NE];
    const float4* W2v = reinterpret_cast<const float4*>(W2);
    #pragma unroll
    for (int f = 0; f < NE; ++f) {
        float s = 0.0f;
        #pragma unroll
        for (int q = 0; q < NE / 4; ++q) {
            float4 w = __ldg(W2v + f * (NE / 4) + q);
            s = fmaf(h[4 * q + 0], w.x, s);
            s = fmaf(h[4 * q + 1], w.y, s);
            s = fmaf(h[4 * q + 2], w.z, s);
            s = fmaf(h[4 * q + 3], w.w, s);
        }
        v[f] = s / 0.7f;
        id[f] = f;
    }

    // Batcher odd-even mergesort, n=16, 63 comparators, descending.
    CE(0,1) CE(2,3) CE(4,5) CE(6,7) CE(8,9) CE(10,11) CE(12,13) CE(14,15)
    CE(0,2) CE(1,3) CE(4,6) CE(5,7) CE(8,10) CE(9,11) CE(12,14) CE(13,15)
    CE(1,2) CE(5,6) CE(9,10) CE(13,14)
    CE(0,4) CE(1,5) CE(2,6) CE(3,7) CE(8,12) CE(9,13) CE(10,14) CE(11,15)
    CE(2,4) CE(3,5) CE(10,12) CE(11,13)
    CE(1,2) CE(3,4) CE(5,6) CE(9,10) CE(11,12) CE(13,14)
    CE(0,8) CE(1,9) CE(2,10) CE(3,11) CE(4,12) CE(5,13) CE(6,14) CE(7,15)
    CE(4,8) CE(5,9) CE(6,10) CE(7,11)
    CE(2,4) CE(3,5) CE(6,8) CE(7,9) CE(10,12) CE(11,13)
    CE(1,2) CE(3,4) CE(5,6) CE(7,8) CE(9,10) CE(11,12) CE(13,14)

    // Softmax over sorted logits (max = v[0]).
    float m = v[0];
    float p[NE]; float ssum = 0.0f;
    #pragma unroll
    for (int e = 0; e < NE; ++e) { p[e] = expf(v[e] - m); ssum += p[e]; }
    float inv = 1.0f / ssum;
    #pragma unroll
    for (int e = 0; e < NE; ++e) p[e] *= inv;

    // k from cumulative probability.
    int k = NE;
    float cum = 0.0f;
    #pragma unroll
    for (int e = 0; e < NE; ++e) {
        cum += p[e];
        if (k == NE && cum >= 0.92f) k = e + 1;
    }
    float p1 = p[0], p2 = p[1], p3 = p[2];
    if (p1 >= 0.46f && (p1 - p2) >= 0.1f) k = 1;
    if (k > 2 && ((p1 + p2) >= 0.82f || p3 <= 0.12f || (p2 - p3) <= 0.03f)) k = 2;
    if (k < 1) k = 1;
    if (k > 3) k = 3;

    float* oidx  = out;
    float* osc   = out + (size_t)B * 8;
    float* omask = out + (size_t)B * 16;
    float* okv   = out + (size_t)B * 24;
    #pragma unroll
    for (int j = 0; j < 8; ++j) {
        float msk = (j < k) ? 1.0f : 0.0f;
        oidx[row * 8 + j]  = (float)id[j];
        osc[row * 8 + j]   = p[j] * msk;
        omask[row * 8 + j] = msk;
    }
    okv[row] = (float)k;
}

extern "C" void kernel_launch(void* const* d_in, const int* in_sizes, int n_in,
                              void* d_out, int out_size)
{
    const float* x  = (const float*)d_in[0];
    const float* W1 = (const float*)d_in[1];
    const float* W2 = (const float*)d_in[2];
    float* out = (float*)d_out;

    int B = in_sizes[0] / IN_DIM;                 // 16384

    // Kernel A: 4 warps/block, 2 rows/warp -> 8 rows/block.
    int blocksA = (B + 7) / 8;                    // 2048
    gemm1_kernel<<<blocksA, 128>>>(x, W1, B);

    // Kernel B: 1 thread/row.
    int blocksB = (B + 255) / 256;                // 64
    epilogue_kernel<<<blocksB, 256>>>(W2, out, B);
}